// round 12
// baseline (speedup 1.0000x reference)
#include <cuda_runtime.h>
#include <cuda_fp16.h>
#include <cstdint>

// ---------------- problem constants ----------------
#define N_IMG 32
#define HW_DIM 112
#define C_IN 128
#define C_OUT 256
#define PIX_PER_IMG (HW_DIM * HW_DIM)            // 12544
#define TOT_PIX (N_IMG * PIX_PER_IMG)            // 401408
#define TILES_PER_IMG 49                          // 7x7 tiles of 16x16 px
#define NUM_CTAS (N_IMG * TILES_PER_IMG)          // 1568
#define K_CHUNK 64
#define NUM_CHUNKS 18                             // 2 halves (outer) * 9 taps
#define HALO 18
#define HALO_PIX (HALO * HALO)                    // 324

// ---------------- arch-feature guard ----------------
#if defined(__CUDA_ARCH_FEAT_SM103_ALL) || defined(__CUDA_ARCH_FEAT_SM100_ALL) || \
    defined(__CUDA_ARCH_SPECIFIC__) || defined(__CUDA_ARCH_FAMILY_SPECIFIC__)
#define HAS_TCGEN05 1
#else
#define HAS_TCGEN05 0
#endif

// ---------------- smem layout (bytes) ----------------
#define SM_TMEM   0
#define SM_MBAR   8                    // 2 mbarriers: 8, 16
#define SM_X      1024                 // halo half: 324 px * 128 B = 41472
#define SM_A      43008                // A stages: 2 x 32768 (1024-aligned)
#define A_STAGE_B 32768
#define A_TILE_B  16384
#define SM_B      108544               // B stages: 3 x 32768
#define B_STAGE_B 32768
#define SM_BIAS   206848               // 256 floats
#define SM_TOTAL  207872
#define SM_TBUF   SM_A                 // epilogue reuses A region
#define TBUF_FLT  4224                 // 128*33 floats per tile

// scratch (device global: allocation-free scratch per harness rules)
// packing: [half][tap][co][64]
__device__ __half Wq_g[NUM_CHUNKS * C_OUT * K_CHUNK];         // 576 KB

// ---------------- ptx helpers ----------------
__device__ __forceinline__ uint32_t smem_u32(const void* p) {
    uint32_t a;
    asm("{ .reg .u64 t; cvta.to.shared.u64 t, %1; cvt.u32.u64 %0, t; }"
        : "=r"(a) : "l"(p));
    return a;
}

__device__ __forceinline__ bool elect_one() {
    uint32_t pred;
    asm volatile(
        "{\n\t.reg .pred p;\n\telect.sync _|p, 0xFFFFFFFF;\n\t"
        "selp.b32 %0, 1, 0, p;\n\t}" : "=r"(pred));
    return pred != 0;
}

#define SW128(off) ((off) ^ (((off) >> 3) & 0x70))

__device__ __forceinline__ uint64_t make_desc_sw128(uint32_t addr) {
    uint64_t d = ((uint64_t)2 << 61) | ((uint64_t)1 << 46) |
                 ((uint64_t)64 << 32) | ((uint64_t)1 << 16);
    d |= (uint64_t)((addr >> 4) & 0x3FFF);
    return d;
}

__device__ __forceinline__ void cp_async16(uint32_t smem_addr, const void* gptr) {
    asm volatile("cp.async.cg.shared.global [%0], [%1], 16;"
                 :: "r"(smem_addr), "l"(gptr) : "memory");
}
#define CP_ASYNC_COMMIT() asm volatile("cp.async.commit_group;" ::: "memory")
#define CP_ASYNC_WAIT_1() asm volatile("cp.async.wait_group 1;" ::: "memory")
#define CP_ASYNC_WAIT_0() asm volatile("cp.async.wait_group 0;" ::: "memory")

// shared-space 128-bit copy via explicit state-space instructions
__device__ __forceinline__ void lds128(uint32_t addr, uint32_t& r0, uint32_t& r1,
                                       uint32_t& r2, uint32_t& r3) {
    asm volatile("ld.shared.v4.b32 {%0, %1, %2, %3}, [%4];"
                 : "=r"(r0), "=r"(r1), "=r"(r2), "=r"(r3) : "r"(addr));
}
__device__ __forceinline__ void sts128(uint32_t addr, uint32_t r0, uint32_t r1,
                                       uint32_t r2, uint32_t r3) {
    asm volatile("st.shared.v4.b32 [%0], {%1, %2, %3, %4};"
                 :: "r"(addr), "r"(r0), "r"(r1), "r"(r2), "r"(r3) : "memory");
}

#if HAS_TCGEN05

#define TCGEN05_ALLOC(smem_addr, nCols) \
    asm volatile("tcgen05.alloc.cta_group::1.sync.aligned.shared::cta.b32 [%0], %1;" \
                 :: "r"((uint32_t)(smem_addr)), "r"((uint32_t)(nCols)) : "memory")
#define TCGEN05_DEALLOC(tmem_addr, nCols) \
    asm volatile("tcgen05.dealloc.cta_group::1.sync.aligned.b32 %0, %1;" \
                 :: "r"(tmem_addr), "r"((uint32_t)(nCols)))
#define TCGEN05_RELINQUISH() \
    asm volatile("tcgen05.relinquish_alloc_permit.cta_group::1.sync.aligned;")
#define TCGEN05_COMMIT(mbar) \
    asm volatile("tcgen05.commit.cta_group::1.mbarrier::arrive::one.shared::cluster.b64 [%0];" \
                 :: "r"((uint32_t)(mbar)) : "memory")
#define TCGEN05_FENCE_AFTER() \
    asm volatile("tcgen05.fence::after_thread_sync;" ::: "memory")
#define TCGEN05_WAIT_LD() \
    asm volatile("tcgen05.wait::ld.sync.aligned;" ::: "memory")

#define TCGEN05_LD_32X32B_X32(r, tmem_addr) \
    asm volatile( \
        "tcgen05.ld.sync.aligned.32x32b.x32.b32 " \
        "{%0, %1, %2, %3, %4, %5, %6, %7, " \
        " %8, %9, %10, %11, %12, %13, %14, %15, " \
        " %16, %17, %18, %19, %20, %21, %22, %23, " \
        " %24, %25, %26, %27, %28, %29, %30, %31}, [%32];" \
        : "=r"((r)[0]),  "=r"((r)[1]),  "=r"((r)[2]),  "=r"((r)[3]), \
          "=r"((r)[4]),  "=r"((r)[5]),  "=r"((r)[6]),  "=r"((r)[7]), \
          "=r"((r)[8]),  "=r"((r)[9]),  "=r"((r)[10]), "=r"((r)[11]), \
          "=r"((r)[12]), "=r"((r)[13]), "=r"((r)[14]), "=r"((r)[15]), \
          "=r"((r)[16]), "=r"((r)[17]), "=r"((r)[18]), "=r"((r)[19]), \
          "=r"((r)[20]), "=r"((r)[21]), "=r"((r)[22]), "=r"((r)[23]), \
          "=r"((r)[24]), "=r"((r)[25]), "=r"((r)[26]), "=r"((r)[27]), \
          "=r"((r)[28]), "=r"((r)[29]), "=r"((r)[30]), "=r"((r)[31]) \
        : "r"(tmem_addr))

__device__ __forceinline__ void mma_f16_ss(uint32_t d_tmem, uint64_t a_desc,
                                           uint64_t b_desc, uint32_t idesc,
                                           uint32_t enable_d) {
    asm volatile(
        "{\n\t.reg .pred p;\n\t"
        "setp.ne.u32 p, %4, 0;\n\t"
        "tcgen05.mma.cta_group::1.kind::f16 [%0], %1, %2, %3, p;\n\t}"
        :: "r"(d_tmem), "l"(a_desc), "l"(b_desc), "r"(idesc), "r"(enable_d)
        : "memory");
}

#else  // portable-pass stubs (never executed on GB300)

#define TCGEN05_ALLOC(smem_addr, nCols)      do {} while (0)
#define TCGEN05_DEALLOC(tmem_addr, nCols)    do {} while (0)
#define TCGEN05_RELINQUISH()                 do {} while (0)
#define TCGEN05_COMMIT(mbar)                 do {} while (0)
#define TCGEN05_FENCE_AFTER()                do {} while (0)
#define TCGEN05_WAIT_LD()                    do {} while (0)
#define TCGEN05_LD_32X32B_X32(r, tmem_addr) \
    do { _Pragma("unroll") for (int _i = 0; _i < 32; _i++) (r)[_i] = 0u; } while (0)

__device__ __forceinline__ void mma_f16_ss(uint32_t, uint64_t, uint64_t,
                                           uint32_t, uint32_t) {}

#endif  // HAS_TCGEN05

#define FENCE_PROXY_ASYNC_SHARED() \
    asm volatile("fence.proxy.async.shared::cta;" ::: "memory")

#define MBARRIER_INIT(mbar, count) \
    asm volatile("mbarrier.init.shared.b64 [%0], %1;" \
                 :: "r"((uint32_t)(mbar)), "r"((uint32_t)(count)) : "memory")

#define MBARRIER_WAIT_PARITY(mbar_addr, phase_parity) do { \
    uint32_t _mbar = (uint32_t)(mbar_addr); \
    uint32_t _parity = (uint32_t)(phase_parity); \
    uint32_t _done; \
    asm volatile( \
        "{\n\t.reg .pred p;\n\t" \
        "mbarrier.try_wait.parity.acquire.cta.shared::cta.b64 p, [%1], %2;\n\t" \
        "selp.b32 %0, 1, 0, p;\n\t}" \
        : "=r"(_done) : "r"(_mbar), "r"(_parity) : "memory"); \
    if (!_done) { \
        asm volatile( \
            "{\n\t.reg .pred P1;\n\t" \
            "WAIT_LOOP_%=:\n\t" \
            "mbarrier.try_wait.parity.acquire.cta.shared::cta.b64 P1, [%0], %1, 0x989680;\n\t" \
            "@P1 bra.uni WAIT_DONE_%=;\n\t" \
            "bra.uni WAIT_LOOP_%=;\n\t" \
            "WAIT_DONE_%=:\n\t}" \
            :: "r"(_mbar), "r"(_parity) : "memory"); \
    } \
} while (0)

// wait until MMA(j) has committed (arrival #(j/2+1) on mbar[j&1])
#define WAIT_MMA(j) \
    MBARRIER_WAIT_PARITY(smem_base + SM_MBAR + ((j) & 1) * 8, ((j) >> 1) & 1)

// idesc: F32 accum (1<<4), FP16 a/b, N=256 -> (32<<17), M=128 -> (8<<24)
#define MMA_IDESC 0x8400010u

// ---------------- prep kernel: binarize + pack W ----------------
// packing: chunk = half*9 + tap; Wq_g[chunk][co][64]
__global__ void quant_w_kernel(const float* __restrict__ W) {
    int o = blockIdx.x * 256 + threadIdx.x;
    if (o < NUM_CHUNKS * C_OUT * K_CHUNK) {
        int col = o & 63;
        int co = (o >> 6) & 255;
        int tc = o >> 14;                       // 0..17
        int half = tc / 9, tap = tc % 9;
        int ci = half * 64 + col;
        float w = W[(tap * C_IN + ci) * C_OUT + co];
        Wq_g[o] = __float2half(w > 0.f ? 1.f : (w < 0.f ? -1.f : 0.f));
    }
}

// ---------------- main fused conv kernel ----------------
// One 16x16 pixel tile per CTA. Half-split halo (64 ci, 41 KB) loaded twice;
// A tiles built SMEM->SMEM; B triple-buffered via prefetched cp.async.
__global__ void __launch_bounds__(256, 1)
bconv_main_kernel(const float* __restrict__ x, const float* __restrict__ bias,
                  float* __restrict__ out) {
    extern __shared__ char smem[];
    uint32_t smem_base = smem_u32(smem);
    int tid = threadIdx.x;
    int wid = tid >> 5, lid = tid & 31;

    if (wid == 0) {
        TCGEN05_ALLOC(smem_base + SM_TMEM, 512);
        TCGEN05_RELINQUISH();
    }
    if (tid == 0) {
        MBARRIER_INIT(smem_base + SM_MBAR + 0, 1);
        MBARRIER_INIT(smem_base + SM_MBAR + 8, 1);
    }
    __syncthreads();
    uint32_t tmem_base;
    asm volatile("ld.shared.b32 %0, [%1];" : "=r"(tmem_base)
                 : "r"(smem_base + SM_TMEM));

    // tile coordinates
    int img = blockIdx.x / TILES_PER_IMG;
    int t49 = blockIdx.x % TILES_PER_IMG;
    int ty0 = (t49 / 7) * 16, tx0 = (t49 % 7) * 16;
    size_t img_px = (size_t)img * PIX_PER_IMG;
    const float* xg = x + img_px * C_IN;

    // B fill smem offsets (8 per thread, within one B stage)
    uint32_t stsB[8];
    #pragma unroll
    for (int i = 0; i < 8; i++) {
        int item = tid + i * 256;
        stsB[i] = smem_base + SM_B +
                  SW128((uint32_t)(item >> 3) * 128 + (item & 7) * 16);
    }

    // issue B(chunk) into stage s via cp.async
    auto issue_B = [&](int chunk, int s) {
        const __half* wsrc = Wq_g + (size_t)chunk * (C_OUT * K_CHUNK) + tid * 8;
        uint32_t boff = (uint32_t)s * B_STAGE_B;
        #pragma unroll
        for (int i = 0; i < 8; i++)
            cp_async16(stsB[i] + boff, wsrc + i * 2048);
        CP_ASYNC_COMMIT();
    };

    // halo load for one ci-half: 324 px * 64 ci fp32 -> fp16 SMEM
    auto load_halo = [&](int half) {
        int hbase = half * 64;
        for (int idx = tid; idx < HALO_PIX * 16; idx += 256) {
            int pix = idx >> 4, c4 = idx & 15;
            int py = ty0 - 1 + pix / HALO;
            int px = tx0 - 1 + pix % HALO;
            uint2 u = make_uint2(0u, 0u);
            if ((unsigned)py < (unsigned)HW_DIM && (unsigned)px < (unsigned)HW_DIM) {
                float4 v = *reinterpret_cast<const float4*>(
                    xg + ((size_t)py * HW_DIM + px) * C_IN + hbase + c4 * 4);
                __half2 h0 = __floats2half2_rn(v.x, v.y);
                __half2 h1 = __floats2half2_rn(v.z, v.w);
                u.x = *reinterpret_cast<uint32_t*>(&h0);
                u.y = *reinterpret_cast<uint32_t*>(&h1);
            }
            *reinterpret_cast<uint2*>(smem + SM_X + pix * 128 + c4 * 8) = u;
        }
    };

    // ---- prologue: B0/B1 in flight, then halo half 0 ----
    issue_B(0, 0);
    issue_B(1, 1);
    load_halo(0);
    __syncthreads();

    // ---- precompute per-thread A-build shared addresses ----
    int seg = tid & 7;                            // 16B segment in 128B row
    int prow = tid >> 3;                          // base row (step 32)
    uint32_t ldsA[8], stsA[8];                    // [t*4+i]
    #pragma unroll
    for (int t = 0; t < 2; t++) {
        #pragma unroll
        for (int i = 0; i < 4; i++) {
            int r = prow + i * 32;
            int lp = t * 128 + r;
            int oy = lp >> 4, ox = lp & 15;
            ldsA[t * 4 + i] = smem_base + SM_X +
                              (uint32_t)(oy * HALO + ox) * 128 + seg * 16;
            stsA[t * 4 + i] = smem_base + SM_A + t * A_TILE_B +
                              SW128((uint32_t)r * 128 + seg * 16);
        }
    }

    #pragma unroll 1
    for (int c = 0; c < NUM_CHUNKS; c++) {
        int tap = c % 9;
        int oyk = tap / 3, oxk = tap % 3;

        // buffer guard: A[c&1] and Bstage[(c+1)%3] were last read by MMA(c-2)
        if (c >= 2) WAIT_MMA(c - 2);

        // mid-kernel halo swap to ci-half 1
        if (c == 9) {
            load_halo(1);
            __syncthreads();
        }

        // A build: halo -> swizzled A tiles
        {
            uint32_t ldelta = (uint32_t)(oyk * HALO + oxk) * 128;
            uint32_t soff = (uint32_t)(c & 1) * A_STAGE_B;
            #pragma unroll
            for (int k = 0; k < 8; k++) {
                uint32_t r0, r1, r2, r3;
                lds128(ldsA[k] + ldelta, r0, r1, r2, r3);
                sts128(stsA[k] + soff, r0, r1, r2, r3);
            }
        }

        // prefetch B(c+1) (B0/B1 pre-issued in prologue)
        if (c >= 1 && c + 1 < NUM_CHUNKS) issue_B(c + 1, (c + 1) % 3);

        // B(c) complete (B(c+1) may stay outstanding)
        if (c + 1 < NUM_CHUNKS) { CP_ASYNC_WAIT_1(); } else { CP_ASYNC_WAIT_0(); }
        FENCE_PROXY_ASYNC_SHARED();
        __syncthreads();

        if (wid == 0 && elect_one()) {
            uint32_t abase = smem_base + SM_A + (c & 1) * A_STAGE_B;
            uint64_t a0 = make_desc_sw128(abase);
            uint64_t a1 = make_desc_sw128(abase + A_TILE_B);
            uint64_t bd = make_desc_sw128(smem_base + SM_B + (c % 3) * B_STAGE_B);
            uint32_t en = (c > 0);
            #pragma unroll
            for (int s = 0; s < 4; s++)
                mma_f16_ss(tmem_base, a0 + s * 2, bd + s * 2,
                           MMA_IDESC, en | (s > 0));
            #pragma unroll
            for (int s = 0; s < 4; s++)
                mma_f16_ss(tmem_base + 256, a1 + s * 2, bd + s * 2,
                           MMA_IDESC, en | (s > 0));
            TCGEN05_COMMIT(smem_base + SM_MBAR + (c & 1) * 8);
        }
    }

    // drain final MMAs
    WAIT_MMA(16);
    WAIT_MMA(17);
    TCGEN05_FENCE_AFTER();

    // ---- epilogue: both warpgroups drain their tile in parallel ----
    float* bsm = reinterpret_cast<float*>(smem + SM_BIAS);
    bsm[tid] = bias[tid];
    __syncthreads();

    int wg = wid >> 2;                            // tile index
    int sp = wid & 3;                             // subpartition
    float* tb = reinterpret_cast<float*>(smem + SM_TBUF) + wg * TBUF_FLT;
    float* tb_all = reinterpret_cast<float*>(smem + SM_TBUF);

    #pragma unroll 1
    for (int cb = 0; cb < 8; cb++) {
        uint32_t regs[32];
        TCGEN05_LD_32X32B_X32(regs, tmem_base + wg * 256 + cb * 32);
        TCGEN05_WAIT_LD();
        int row = sp * 32 + lid;
        #pragma unroll
        for (int j = 0; j < 32; j++)
            tb[row * 33 + j] = __uint_as_float(regs[j]) + bsm[cb * 32 + j];
        __syncthreads();
        #pragma unroll
        for (int i = 0; i < 32; i++) {
            int item = tid + i * 256;             // 2 tiles x 128 px x 32 cols
            int t2 = item >> 12, rem = item & 4095;
            int p = rem >> 5, cc = rem & 31;
            int lp = t2 * 128 + p;
            int oy = lp >> 4, ox = lp & 15;
            size_t gp = img_px + (size_t)(ty0 + oy) * HW_DIM + (tx0 + ox);
            out[gp * C_OUT + cb * 32 + cc] = tb_all[t2 * TBUF_FLT + p * 33 + cc];
        }
        __syncthreads();
    }

    __syncthreads();                              // no warp may still touch TMEM
    if (wid == 0) {
        TCGEN05_DEALLOC(tmem_base, 512);
    }
}

// ---------------- launch ----------------
extern "C" void kernel_launch(void* const* d_in, const int* in_sizes, int n_in,
                              void* d_out, int out_size) {
    const float* x = (const float*)d_in[0];
    const float* W = (const float*)d_in[1];
    const float* b = (const float*)d_in[2];
    float* out = (float*)d_out;

    cudaFuncSetAttribute(bconv_main_kernel,
                         cudaFuncAttributeMaxDynamicSharedMemorySize, SM_TOTAL);

    quant_w_kernel<<<(NUM_CHUNKS * C_OUT * K_CHUNK) / 256, 256>>>(W);
    bconv_main_kernel<<<NUM_CTAS, 256, SM_TOTAL>>>(x, b, out);
}

// round 13
// speedup vs baseline: 1.2876x; 1.2876x over previous
#include <cuda_runtime.h>
#include <cuda_fp16.h>
#include <cstdint>

// ---------------- problem constants ----------------
#define N_IMG 32
#define HW_DIM 112
#define C_IN 128
#define C_OUT 256
#define PIX_PER_IMG (HW_DIM * HW_DIM)            // 12544
#define TOT_PIX (N_IMG * PIX_PER_IMG)            // 401408
#define NUM_PAIRS (TOT_PIX / 256)                // 1568 CTAs, 2 M-tiles each
#define K_CHUNK 64
#define NUM_CHUNKS 18                             // 9 taps * 2 halves

// ---------------- arch-feature guard ----------------
#if defined(__CUDA_ARCH_FEAT_SM103_ALL) || defined(__CUDA_ARCH_FEAT_SM100_ALL) || \
    defined(__CUDA_ARCH_SPECIFIC__) || defined(__CUDA_ARCH_FAMILY_SPECIFIC__)
#define HAS_TCGEN05 1
#else
#define HAS_TCGEN05 0
#endif

// ---------------- smem layout (bytes) ----------------
#define SM_TMEM   0
#define SM_MBAR   8                   // 3 mbarriers: 8, 16, 24
#define SM_STAGE  1024                // 3 stages x 65536
#define STAGE_BYTES 65536             // A0 16K | A1 16K | B 32K
#define A_TILE_B  16384
#define B_OFF     32768
#define SM_BIAS   (SM_STAGE + 3 * STAGE_BYTES)          // 197632
#define SM_TOTAL  (SM_BIAS + 1024)                      // 198656
#define SM_TBUF   SM_STAGE            // epilogue: 8 warps x 4096 B (reuses stage0)

// scratch (device globals: allocation-free scratch per harness rules)
__device__ __half Xh_g[(size_t)TOT_PIX * C_IN];               // ~103 MB
__device__ __half Wq_g[NUM_CHUNKS * C_OUT * K_CHUNK];         // 576 KB

// ---------------- ptx helpers ----------------
__device__ __forceinline__ uint32_t smem_u32(const void* p) {
    uint32_t a;
    asm("{ .reg .u64 t; cvta.to.shared.u64 t, %1; cvt.u32.u64 %0, t; }"
        : "=r"(a) : "l"(p));
    return a;
}

__device__ __forceinline__ bool elect_one() {
    uint32_t pred;
    asm volatile(
        "{\n\t.reg .pred p;\n\telect.sync _|p, 0xFFFFFFFF;\n\t"
        "selp.b32 %0, 1, 0, p;\n\t}" : "=r"(pred));
    return pred != 0;
}

#define SW128(off) ((off) ^ (((off) >> 3) & 0x70))

__device__ __forceinline__ uint64_t make_desc_sw128(uint32_t addr) {
    uint64_t d = ((uint64_t)2 << 61) | ((uint64_t)1 << 46) |
                 ((uint64_t)64 << 32) | ((uint64_t)1 << 16);
    d |= (uint64_t)((addr >> 4) & 0x3FFF);
    return d;
}

// cp.async 16B with zero-fill when !ok (src_size = 0 reads nothing)
__device__ __forceinline__ void cp_async16z(uint32_t smem_addr, const void* gptr,
                                            bool ok) {
    int sz = ok ? 16 : 0;
    asm volatile("cp.async.cg.shared.global [%0], [%1], 16, %2;"
                 :: "r"(smem_addr), "l"(gptr), "r"(sz) : "memory");
}
__device__ __forceinline__ void cp_async16(uint32_t smem_addr, const void* gptr) {
    asm volatile("cp.async.cg.shared.global [%0], [%1], 16;"
                 :: "r"(smem_addr), "l"(gptr) : "memory");
}
#define CP_ASYNC_COMMIT() asm volatile("cp.async.commit_group;" ::: "memory")
#define CP_ASYNC_WAIT_1() asm volatile("cp.async.wait_group 1;" ::: "memory")
#define CP_ASYNC_WAIT_0() asm volatile("cp.async.wait_group 0;" ::: "memory")

// shared-space 128-bit ops (explicit state space)
__device__ __forceinline__ void lds128(uint32_t addr, uint32_t& r0, uint32_t& r1,
                                       uint32_t& r2, uint32_t& r3) {
    asm volatile("ld.shared.v4.b32 {%0, %1, %2, %3}, [%4];"
                 : "=r"(r0), "=r"(r1), "=r"(r2), "=r"(r3) : "r"(addr));
}
__device__ __forceinline__ void sts128(uint32_t addr, uint32_t r0, uint32_t r1,
                                       uint32_t r2, uint32_t r3) {
    asm volatile("st.shared.v4.b32 [%0], {%1, %2, %3, %4};"
                 :: "r"(addr), "r"(r0), "r"(r1), "r"(r2), "r"(r3) : "memory");
}

#if HAS_TCGEN05

#define TCGEN05_ALLOC(smem_addr, nCols) \
    asm volatile("tcgen05.alloc.cta_group::1.sync.aligned.shared::cta.b32 [%0], %1;" \
                 :: "r"((uint32_t)(smem_addr)), "r"((uint32_t)(nCols)) : "memory")
#define TCGEN05_DEALLOC(tmem_addr, nCols) \
    asm volatile("tcgen05.dealloc.cta_group::1.sync.aligned.b32 %0, %1;" \
                 :: "r"(tmem_addr), "r"((uint32_t)(nCols)))
#define TCGEN05_RELINQUISH() \
    asm volatile("tcgen05.relinquish_alloc_permit.cta_group::1.sync.aligned;")
#define TCGEN05_COMMIT(mbar) \
    asm volatile("tcgen05.commit.cta_group::1.mbarrier::arrive::one.shared::cluster.b64 [%0];" \
                 :: "r"((uint32_t)(mbar)) : "memory")
#define TCGEN05_FENCE_AFTER() \
    asm volatile("tcgen05.fence::after_thread_sync;" ::: "memory")
#define TCGEN05_WAIT_LD() \
    asm volatile("tcgen05.wait::ld.sync.aligned;" ::: "memory")

#define TCGEN05_LD_32X32B_X32(r, tmem_addr) \
    asm volatile( \
        "tcgen05.ld.sync.aligned.32x32b.x32.b32 " \
        "{%0, %1, %2, %3, %4, %5, %6, %7, " \
        " %8, %9, %10, %11, %12, %13, %14, %15, " \
        " %16, %17, %18, %19, %20, %21, %22, %23, " \
        " %24, %25, %26, %27, %28, %29, %30, %31}, [%32];" \
        : "=r"((r)[0]),  "=r"((r)[1]),  "=r"((r)[2]),  "=r"((r)[3]), \
          "=r"((r)[4]),  "=r"((r)[5]),  "=r"((r)[6]),  "=r"((r)[7]), \
          "=r"((r)[8]),  "=r"((r)[9]),  "=r"((r)[10]), "=r"((r)[11]), \
          "=r"((r)[12]), "=r"((r)[13]), "=r"((r)[14]), "=r"((r)[15]), \
          "=r"((r)[16]), "=r"((r)[17]), "=r"((r)[18]), "=r"((r)[19]), \
          "=r"((r)[20]), "=r"((r)[21]), "=r"((r)[22]), "=r"((r)[23]), \
          "=r"((r)[24]), "=r"((r)[25]), "=r"((r)[26]), "=r"((r)[27]), \
          "=r"((r)[28]), "=r"((r)[29]), "=r"((r)[30]), "=r"((r)[31]) \
        : "r"(tmem_addr))

__device__ __forceinline__ void mma_f16_ss(uint32_t d_tmem, uint64_t a_desc,
                                           uint64_t b_desc, uint32_t idesc,
                                           uint32_t enable_d) {
    asm volatile(
        "{\n\t.reg .pred p;\n\t"
        "setp.ne.u32 p, %4, 0;\n\t"
        "tcgen05.mma.cta_group::1.kind::f16 [%0], %1, %2, %3, p;\n\t}"
        :: "r"(d_tmem), "l"(a_desc), "l"(b_desc), "r"(idesc), "r"(enable_d)
        : "memory");
}

#else  // portable-pass stubs (never executed on GB300)

#define TCGEN05_ALLOC(smem_addr, nCols)      do {} while (0)
#define TCGEN05_DEALLOC(tmem_addr, nCols)    do {} while (0)
#define TCGEN05_RELINQUISH()                 do {} while (0)
#define TCGEN05_COMMIT(mbar)                 do {} while (0)
#define TCGEN05_FENCE_AFTER()                do {} while (0)
#define TCGEN05_WAIT_LD()                    do {} while (0)
#define TCGEN05_LD_32X32B_X32(r, tmem_addr) \
    do { _Pragma("unroll") for (int _i = 0; _i < 32; _i++) (r)[_i] = 0u; } while (0)

__device__ __forceinline__ void mma_f16_ss(uint32_t, uint64_t, uint64_t,
                                           uint32_t, uint32_t) {}

#endif  // HAS_TCGEN05

#define FENCE_PROXY_ASYNC_SHARED() \
    asm volatile("fence.proxy.async.shared::cta;" ::: "memory")

#define MBARRIER_INIT(mbar, count) \
    asm volatile("mbarrier.init.shared.b64 [%0], %1;" \
                 :: "r"((uint32_t)(mbar)), "r"((uint32_t)(count)) : "memory")

#define MBARRIER_WAIT_PARITY(mbar_addr, phase_parity) do { \
    uint32_t _mbar = (uint32_t)(mbar_addr); \
    uint32_t _parity = (uint32_t)(phase_parity); \
    uint32_t _done; \
    asm volatile( \
        "{\n\t.reg .pred p;\n\t" \
        "mbarrier.try_wait.parity.acquire.cta.shared::cta.b64 p, [%1], %2;\n\t" \
        "selp.b32 %0, 1, 0, p;\n\t}" \
        : "=r"(_done) : "r"(_mbar), "r"(_parity) : "memory"); \
    if (!_done) { \
        asm volatile( \
            "{\n\t.reg .pred P1;\n\t" \
            "WAIT_LOOP_%=:\n\t" \
            "mbarrier.try_wait.parity.acquire.cta.shared::cta.b64 P1, [%0], %1, 0x989680;\n\t" \
            "@P1 bra.uni WAIT_DONE_%=;\n\t" \
            "bra.uni WAIT_LOOP_%=;\n\t" \
            "WAIT_DONE_%=:\n\t}" \
            :: "r"(_mbar), "r"(_parity) : "memory"); \
    } \
} while (0)

// wait until MMA chunk j has committed (mbar j%3, arrival #(j/3+1))
#define WAIT_MMA(j) \
    MBARRIER_WAIT_PARITY(smem_base + SM_MBAR + ((j) % 3) * 8, ((j) / 3) & 1)

// idesc: F32 accum (1<<4), FP16 a/b, N=256 -> (32<<17), M=128 -> (8<<24)
#define MMA_IDESC 0x8400010u

// ---------------- prep kernels ----------------
__global__ void convert_x_kernel(const float4* __restrict__ x, int n4) {
    int i = blockIdx.x * 256 + threadIdx.x;
    if (i < n4) {
        float4 v = x[i];
        __half2 h0 = __floats2half2_rn(v.x, v.y);
        __half2 h1 = __floats2half2_rn(v.z, v.w);
        uint2 u;
        u.x = *reinterpret_cast<uint32_t*>(&h0);
        u.y = *reinterpret_cast<uint32_t*>(&h1);
        reinterpret_cast<uint2*>(Xh_g)[i] = u;
    }
}

__global__ void quant_w_kernel(const float* __restrict__ W) {
    int o = blockIdx.x * 256 + threadIdx.x;
    if (o < NUM_CHUNKS * C_OUT * K_CHUNK) {
        int col = o & 63;
        int co = (o >> 6) & 255;
        int tc = o >> 14;                       // chunk = tap*2 + half
        int tap = tc >> 1, ch = tc & 1;
        int ci = ch * 64 + col;
        float w = W[(tap * C_IN + ci) * C_OUT + co];
        Wq_g[o] = __float2half(w > 0.f ? 1.f : (w < 0.f ? -1.f : 0.f));
    }
}

// ---------------- main implicit-GEMM conv kernel ----------------
// 2 M-tiles/CTA (shared B), 3-stage cp.async pipeline, warp-private epilogue.
__global__ void __launch_bounds__(256, 1)
bconv_main_kernel(const float* __restrict__ bias, float* __restrict__ out) {
    extern __shared__ char smem[];
    uint32_t smem_base = smem_u32(smem);
    int tid = threadIdx.x;
    int wid = tid >> 5, lid = tid & 31;

    if (wid == 0) {
        TCGEN05_ALLOC(smem_base + SM_TMEM, 512);
        TCGEN05_RELINQUISH();
    }
    if (tid == 0) {
        MBARRIER_INIT(smem_base + SM_MBAR + 0, 1);
        MBARRIER_INIT(smem_base + SM_MBAR + 8, 1);
        MBARRIER_INIT(smem_base + SM_MBAR + 16, 1);
    }
    __syncthreads();
    uint32_t tmem_base;
    asm volatile("ld.shared.b32 %0, [%1];" : "=r"(tmem_base)
                 : "r"(smem_base + SM_TMEM));

    int pix_base = blockIdx.x * 256;

    // per-thread A-fill coordinates: 2 tiles x 4 row-steps
    int hA[8], wA[8];
    size_t rowA[8];
    int seg = tid & 7;                            // 16B segment in 128B row
    int prow = tid >> 3;                          // base row (step 32)
    #pragma unroll
    for (int t = 0; t < 2; t++) {
        #pragma unroll
        for (int i = 0; i < 4; i++) {
            int gp = pix_base + t * 128 + prow + i * 32;
            int n = gp / PIX_PER_IMG;
            int r = gp % PIX_PER_IMG;
            hA[t * 4 + i] = r / HW_DIM;
            wA[t * 4 + i] = r % HW_DIM;
            rowA[t * 4 + i] = (size_t)n * PIX_PER_IMG * C_IN;
        }
    }

    // async fill of one chunk-stage (all 256 threads, 16 cp.async each)
    auto fill_stage = [&](int c, int buf) {
        int tap = c >> 1, half_k = c & 1;
        int kh = tap / 3 - 1, kw = tap % 3 - 1;
        uint32_t sb = smem_base + SM_STAGE + buf * STAGE_BYTES;
        #pragma unroll
        for (int t = 0; t < 2; t++) {
            #pragma unroll
            for (int i = 0; i < 4; i++) {
                int idx = t * 4 + i;
                int hh = hA[idx] + kh, ww = wA[idx] + kw;
                bool ok = ((unsigned)hh < (unsigned)HW_DIM) &&
                          ((unsigned)ww < (unsigned)HW_DIM);
                const __half* src = Xh_g + rowA[idx] +
                    ((size_t)(ok ? hh : 0) * HW_DIM + (ok ? ww : 0)) * C_IN +
                    half_k * 64 + seg * 8;
                uint32_t off = (uint32_t)(prow + i * 32) * 128 + seg * 16;
                cp_async16z(sb + t * A_TILE_B + SW128(off), src, ok);
            }
        }
        const __half* wsrc = Wq_g + (size_t)c * (C_OUT * K_CHUNK);
        #pragma unroll
        for (int i = 0; i < 8; i++) {
            int item = tid + i * 256;             // 0..2047
            uint32_t off = (uint32_t)(item >> 3) * 128 + (item & 7) * 16;
            cp_async16(sb + B_OFF + SW128(off), wsrc + item * 8);
        }
    };

    // prologue: stages 0 and 1 in flight
    fill_stage(0, 0); CP_ASYNC_COMMIT();
    fill_stage(1, 1); CP_ASYNC_COMMIT();

    #pragma unroll 1
    for (int c = 0; c < NUM_CHUNKS; c++) {
        int buf = c % 3;
        if (c < NUM_CHUNKS - 1) { CP_ASYNC_WAIT_1(); } else { CP_ASYNC_WAIT_0(); }
        FENCE_PROXY_ASYNC_SHARED();
        __syncthreads();                          // stage c ready everywhere

        if (wid == 0 && elect_one()) {
            uint32_t sb = smem_base + SM_STAGE + buf * STAGE_BYTES;
            uint64_t a0 = make_desc_sw128(sb);
            uint64_t a1 = make_desc_sw128(sb + A_TILE_B);
            uint64_t bd = make_desc_sw128(sb + B_OFF);
            uint32_t en = (c > 0);
            #pragma unroll
            for (int s = 0; s < 4; s++)
                mma_f16_ss(tmem_base, a0 + s * 2, bd + s * 2,
                           MMA_IDESC, en | (s > 0));
            #pragma unroll
            for (int s = 0; s < 4; s++)
                mma_f16_ss(tmem_base + 256, a1 + s * 2, bd + s * 2,
                           MMA_IDESC, en | (s > 0));
            TCGEN05_COMMIT(smem_base + SM_MBAR + buf * 8);
        }

        if (c + 2 < NUM_CHUNKS) {
            int nb = (c + 2) % 3;
            if (c >= 1) WAIT_MMA(c - 1);          // stage (c+2)%3 last read by MMA(c-1)
            fill_stage(c + 2, nb);
            CP_ASYNC_COMMIT();
        }
    }

    // drain: commit(17) implies all prior MMAs complete
    WAIT_MMA(17);
    TCGEN05_FENCE_AFTER();

    // ---- epilogue: warp-private transpose, no block barriers ----
    float* bsm = reinterpret_cast<float*>(smem + SM_BIAS);
    bsm[tid] = bias[tid];
    __syncthreads();

    int wg = wid >> 2;                            // tile index (0/1)
    int sp = wid & 3;                             // subpartition (row group)
    uint32_t tbw = smem_base + SM_TBUF + (uint32_t)wid * 4096;  // 32 rows x 128B
    int prow_g = pix_base + wg * 128 + sp * 32;   // this warp's first pixel row

    #pragma unroll 1
    for (int cb = 0; cb < 8; cb++) {
        uint32_t regs[32];
        TCGEN05_LD_32X32B_X32(regs, tmem_base + wg * 256 + cb * 32);
        TCGEN05_WAIT_LD();
        // rows: lane lid; store col-chunk k at rotated position (k+lid)&7
        #pragma unroll
        for (int k = 0; k < 8; k++) {
            uint32_t a0 = __float_as_uint(__uint_as_float(regs[4 * k + 0]) + bsm[cb * 32 + 4 * k + 0]);
            uint32_t a1 = __float_as_uint(__uint_as_float(regs[4 * k + 1]) + bsm[cb * 32 + 4 * k + 1]);
            uint32_t a2 = __float_as_uint(__uint_as_float(regs[4 * k + 2]) + bsm[cb * 32 + 4 * k + 2]);
            uint32_t a3 = __float_as_uint(__uint_as_float(regs[4 * k + 3]) + bsm[cb * 32 + 4 * k + 3]);
            sts128(tbw + (uint32_t)lid * 128 + (((k + lid) & 7) << 4), a0, a1, a2, a3);
        }
        __syncwarp();
        // read transposed: iter k -> rows k*4 + lid/8, col-chunk lid&7
        #pragma unroll
        for (int k = 0; k < 8; k++) {
            int p = k * 4 + (lid >> 3);
            int cc = lid & 7;
            uint32_t r0, r1, r2, r3;
            lds128(tbw + (uint32_t)p * 128 + (((cc + p) & 7) << 4), r0, r1, r2, r3);
            float4 v = make_float4(__uint_as_float(r0), __uint_as_float(r1),
                                   __uint_as_float(r2), __uint_as_float(r3));
            *reinterpret_cast<float4*>(
                out + (size_t)(prow_g + p) * C_OUT + cb * 32 + cc * 4) = v;
        }
        __syncwarp();
    }

    __syncthreads();                              // no warp may still touch TMEM
    if (wid == 0) {
        TCGEN05_DEALLOC(tmem_base, 512);
    }
}

// ---------------- launch ----------------
extern "C" void kernel_launch(void* const* d_in, const int* in_sizes, int n_in,
                              void* d_out, int out_size) {
    const float* x = (const float*)d_in[0];
    const float* W = (const float*)d_in[1];
    const float* b = (const float*)d_in[2];
    float* out = (float*)d_out;

    cudaFuncSetAttribute(bconv_main_kernel,
                         cudaFuncAttributeMaxDynamicSharedMemorySize, SM_TOTAL);

    int n4 = (TOT_PIX * C_IN) / 4;
    convert_x_kernel<<<n4 / 256, 256>>>(reinterpret_cast<const float4*>(x), n4);
    quant_w_kernel<<<(NUM_CHUNKS * C_OUT * K_CHUNK) / 256, 256>>>(W);
    bconv_main_kernel<<<NUM_PAIRS, 256, SM_TOTAL>>>(b, out);
}

// round 15
// speedup vs baseline: 1.4687x; 1.1406x over previous
#include <cuda_runtime.h>
#include <cuda_fp16.h>
#include <cstdint>

// ---------------- problem constants ----------------
#define N_IMG 32
#define HW_DIM 112
#define C_IN 128
#define C_OUT 256
#define PIX_PER_IMG (HW_DIM * HW_DIM)            // 12544
#define TOT_PIX (N_IMG * PIX_PER_IMG)            // 401408
#define NUM_PAIRS (TOT_PIX / 256)                // 1568 CTAs, 2 M-tiles each
#define K_CHUNK 64
#define NUM_CHUNKS 18                             // 9 taps * 2 halves
#define NTHREADS 288                              // 8 producer warps + 1 MMA warp

// ---------------- arch-feature guard ----------------
#if defined(__CUDA_ARCH_FEAT_SM103_ALL) || defined(__CUDA_ARCH_FEAT_SM100_ALL) || \
    defined(__CUDA_ARCH_SPECIFIC__) || defined(__CUDA_ARCH_FAMILY_SPECIFIC__)
#define HAS_TCGEN05 1
#else
#define HAS_TCGEN05 0
#endif

// ---------------- smem layout (bytes) ----------------
#define SM_TMEM   0
// fill mbarriers: 8,16,24 ; mma mbarriers: 32,40,48
#define SM_FMBAR  8
#define SM_MMBAR  32
#define SM_STAGE  1024                // 3 stages x 65536
#define STAGE_BYTES 65536             // A0 16K | A1 16K | B 32K
#define A_TILE_B  16384
#define B_OFF     32768
#define SM_BIAS   (SM_STAGE + 3 * STAGE_BYTES)          // 197632
#define SM_TOTAL  (SM_BIAS + 1024)                      // 198656
#define SM_TBUF   SM_STAGE            // epilogue: 8 warps x 4096 B (reuses stage0)

// scratch (device globals: allocation-free scratch per harness rules)
__device__ __half Xh_g[(size_t)TOT_PIX * C_IN];               // ~103 MB
__device__ __half Wq_g[NUM_CHUNKS * C_OUT * K_CHUNK];         // 576 KB

// ---------------- ptx helpers ----------------
__device__ __forceinline__ uint32_t smem_u32(const void* p) {
    uint32_t a;
    asm("{ .reg .u64 t; cvta.to.shared.u64 t, %1; cvt.u32.u64 %0, t; }"
        : "=r"(a) : "l"(p));
    return a;
}

__device__ __forceinline__ bool elect_one() {
    uint32_t pred;
    asm volatile(
        "{\n\t.reg .pred p;\n\telect.sync _|p, 0xFFFFFFFF;\n\t"
        "selp.b32 %0, 1, 0, p;\n\t}" : "=r"(pred));
    return pred != 0;
}

#define SW128(off) ((off) ^ (((off) >> 3) & 0x70))

__device__ __forceinline__ uint64_t make_desc_sw128(uint32_t addr) {
    uint64_t d = ((uint64_t)2 << 61) | ((uint64_t)1 << 46) |
                 ((uint64_t)64 << 32) | ((uint64_t)1 << 16);
    d |= (uint64_t)((addr >> 4) & 0x3FFF);
    return d;
}

// cp.async 16B with zero-fill when !ok (src_size = 0 reads nothing)
__device__ __forceinline__ void cp_async16z(uint32_t smem_addr, const void* gptr,
                                            bool ok) {
    int sz = ok ? 16 : 0;
    asm volatile("cp.async.cg.shared.global [%0], [%1], 16, %2;"
                 :: "r"(smem_addr), "l"(gptr), "r"(sz) : "memory");
}
__device__ __forceinline__ void cp_async16(uint32_t smem_addr, const void* gptr) {
    asm volatile("cp.async.cg.shared.global [%0], [%1], 16;"
                 :: "r"(smem_addr), "l"(gptr) : "memory");
}
// async arrival on mbar when this thread's prior cp.asyncs complete.
// .noinc: counts against the init() expected count (256 producers/phase).
#define CP_ASYNC_MBAR_ARRIVE(mbar) \
    asm volatile("cp.async.mbarrier.arrive.noinc.shared::cta.b64 [%0];" \
                 :: "r"((uint32_t)(mbar)) : "memory")

// shared-space 128-bit ops (explicit state space)
__device__ __forceinline__ void lds128(uint32_t addr, uint32_t& r0, uint32_t& r1,
                                       uint32_t& r2, uint32_t& r3) {
    asm volatile("ld.shared.v4.b32 {%0, %1, %2, %3}, [%4];"
                 : "=r"(r0), "=r"(r1), "=r"(r2), "=r"(r3) : "r"(addr));
}
__device__ __forceinline__ void sts128(uint32_t addr, uint32_t r0, uint32_t r1,
                                       uint32_t r2, uint32_t r3) {
    asm volatile("st.shared.v4.b32 [%0], {%1, %2, %3, %4};"
                 :: "r"(addr), "r"(r0), "r"(r1), "r"(r2), "r"(r3) : "memory");
}

#if HAS_TCGEN05

#define TCGEN05_ALLOC(smem_addr, nCols) \
    asm volatile("tcgen05.alloc.cta_group::1.sync.aligned.shared::cta.b32 [%0], %1;" \
                 :: "r"((uint32_t)(smem_addr)), "r"((uint32_t)(nCols)) : "memory")
#define TCGEN05_DEALLOC(tmem_addr, nCols) \
    asm volatile("tcgen05.dealloc.cta_group::1.sync.aligned.b32 %0, %1;" \
                 :: "r"(tmem_addr), "r"((uint32_t)(nCols)))
#define TCGEN05_RELINQUISH() \
    asm volatile("tcgen05.relinquish_alloc_permit.cta_group::1.sync.aligned;")
#define TCGEN05_COMMIT(mbar) \
    asm volatile("tcgen05.commit.cta_group::1.mbarrier::arrive::one.shared::cluster.b64 [%0];" \
                 :: "r"((uint32_t)(mbar)) : "memory")
#define TCGEN05_FENCE_AFTER() \
    asm volatile("tcgen05.fence::after_thread_sync;" ::: "memory")
#define TCGEN05_WAIT_LD() \
    asm volatile("tcgen05.wait::ld.sync.aligned;" ::: "memory")

#define TCGEN05_LD_32X32B_X32(r, tmem_addr) \
    asm volatile( \
        "tcgen05.ld.sync.aligned.32x32b.x32.b32 " \
        "{%0, %1, %2, %3, %4, %5, %6, %7, " \
        " %8, %9, %10, %11, %12, %13, %14, %15, " \
        " %16, %17, %18, %19, %20, %21, %22, %23, " \
        " %24, %25, %26, %27, %28, %29, %30, %31}, [%32];" \
        : "=r"((r)[0]),  "=r"((r)[1]),  "=r"((r)[2]),  "=r"((r)[3]), \
          "=r"((r)[4]),  "=r"((r)[5]),  "=r"((r)[6]),  "=r"((r)[7]), \
          "=r"((r)[8]),  "=r"((r)[9]),  "=r"((r)[10]), "=r"((r)[11]), \
          "=r"((r)[12]), "=r"((r)[13]), "=r"((r)[14]), "=r"((r)[15]), \
          "=r"((r)[16]), "=r"((r)[17]), "=r"((r)[18]), "=r"((r)[19]), \
          "=r"((r)[20]), "=r"((r)[21]), "=r"((r)[22]), "=r"((r)[23]), \
          "=r"((r)[24]), "=r"((r)[25]), "=r"((r)[26]), "=r"((r)[27]), \
          "=r"((r)[28]), "=r"((r)[29]), "=r"((r)[30]), "=r"((r)[31]) \
        : "r"(tmem_addr))

__device__ __forceinline__ void mma_f16_ss(uint32_t d_tmem, uint64_t a_desc,
                                           uint64_t b_desc, uint32_t idesc,
                                           uint32_t enable_d) {
    asm volatile(
        "{\n\t.reg .pred p;\n\t"
        "setp.ne.u32 p, %4, 0;\n\t"
        "tcgen05.mma.cta_group::1.kind::f16 [%0], %1, %2, %3, p;\n\t}"
        :: "r"(d_tmem), "l"(a_desc), "l"(b_desc), "r"(idesc), "r"(enable_d)
        : "memory");
}

#else  // portable-pass stubs (never executed on GB300)

#define TCGEN05_ALLOC(smem_addr, nCols)      do {} while (0)
#define TCGEN05_DEALLOC(tmem_addr, nCols)    do {} while (0)
#define TCGEN05_RELINQUISH()                 do {} while (0)
#define TCGEN05_COMMIT(mbar)                 do {} while (0)
#define TCGEN05_FENCE_AFTER()                do {} while (0)
#define TCGEN05_WAIT_LD()                    do {} while (0)
#define TCGEN05_LD_32X32B_X32(r, tmem_addr) \
    do { _Pragma("unroll") for (int _i = 0; _i < 32; _i++) (r)[_i] = 0u; } while (0)

__device__ __forceinline__ void mma_f16_ss(uint32_t, uint64_t, uint64_t,
                                           uint32_t, uint32_t) {}

#endif  // HAS_TCGEN05

#define FENCE_PROXY_ASYNC_SHARED() \
    asm volatile("fence.proxy.async.shared::cta;" ::: "memory")

#define MBARRIER_INIT(mbar, count) \
    asm volatile("mbarrier.init.shared.b64 [%0], %1;" \
                 :: "r"((uint32_t)(mbar)), "r"((uint32_t)(count)) : "memory")

#define MBARRIER_WAIT_PARITY(mbar_addr, phase_parity) do { \
    uint32_t _mbar = (uint32_t)(mbar_addr); \
    uint32_t _parity = (uint32_t)(phase_parity); \
    uint32_t _done; \
    asm volatile( \
        "{\n\t.reg .pred p;\n\t" \
        "mbarrier.try_wait.parity.acquire.cta.shared::cta.b64 p, [%1], %2;\n\t" \
        "selp.b32 %0, 1, 0, p;\n\t}" \
        : "=r"(_done) : "r"(_mbar), "r"(_parity) : "memory"); \
    if (!_done) { \
        asm volatile( \
            "{\n\t.reg .pred P1;\n\t" \
            "WAIT_LOOP_%=:\n\t" \
            "mbarrier.try_wait.parity.acquire.cta.shared::cta.b64 P1, [%0], %1, 0x989680;\n\t" \
            "@P1 bra.uni WAIT_DONE_%=;\n\t" \
            "bra.uni WAIT_LOOP_%=;\n\t" \
            "WAIT_DONE_%=:\n\t}" \
            :: "r"(_mbar), "r"(_parity) : "memory"); \
    } \
} while (0)

// idesc: F32 accum (1<<4), FP16 a/b, N=256 -> (32<<17), M=128 -> (8<<24)
#define MMA_IDESC 0x8400010u

// ---------------- prep kernels ----------------
__global__ void convert_x_kernel(const float4* __restrict__ x, int n4) {
    int i = blockIdx.x * 256 + threadIdx.x;
    if (i < n4) {
        float4 v = x[i];
        __half2 h0 = __floats2half2_rn(v.x, v.y);
        __half2 h1 = __floats2half2_rn(v.z, v.w);
        uint2 u;
        u.x = *reinterpret_cast<uint32_t*>(&h0);
        u.y = *reinterpret_cast<uint32_t*>(&h1);
        reinterpret_cast<uint2*>(Xh_g)[i] = u;
    }
}

__global__ void quant_w_kernel(const float* __restrict__ W) {
    int o = blockIdx.x * 256 + threadIdx.x;
    if (o < NUM_CHUNKS * C_OUT * K_CHUNK) {
        int col = o & 63;
        int co = (o >> 6) & 255;
        int tc = o >> 14;                       // chunk = tap*2 + half
        int tap = tc >> 1, ch = tc & 1;
        int ci = ch * 64 + col;
        float w = W[(tap * C_IN + ci) * C_OUT + co];
        Wq_g[o] = __float2half(w > 0.f ? 1.f : (w < 0.f ? -1.f : 0.f));
    }
}

// ---------------- main implicit-GEMM conv kernel ----------------
// 2 M-tiles/CTA (shared B); warps 0-7 = producers (cp.async + noinc arrive),
// warp 8 = dedicated MMA warp; sync-free mbarrier pipeline; warp-private epilogue.
__global__ void __launch_bounds__(NTHREADS, 1)
bconv_main_kernel(const float* __restrict__ bias, float* __restrict__ out) {
    extern __shared__ char smem[];
    uint32_t smem_base = smem_u32(smem);
    int tid = threadIdx.x;
    int wid = tid >> 5, lid = tid & 31;

    if (wid == 0) {
        TCGEN05_ALLOC(smem_base + SM_TMEM, 512);
        TCGEN05_RELINQUISH();
    }
    if (tid == 0) {
        #pragma unroll
        for (int s = 0; s < 3; s++) {
            MBARRIER_INIT(smem_base + SM_FMBAR + s * 8, 256);   // producer threads
            MBARRIER_INIT(smem_base + SM_MMBAR + s * 8, 1);     // tcgen05 commit
        }
    }
    __syncthreads();
    uint32_t tmem_base;
    asm volatile("ld.shared.b32 %0, [%1];" : "=r"(tmem_base)
                 : "r"(smem_base + SM_TMEM));

    int pix_base = blockIdx.x * 256;

    // per-thread A-fill coordinates (producers, tid<256): 2 tiles x 4 row-steps
    int hA[8], wA[8];
    size_t rowA[8];
    int seg = tid & 7;
    int prow = (tid & 255) >> 3;
    #pragma unroll
    for (int t = 0; t < 2; t++) {
        #pragma unroll
        for (int i = 0; i < 4; i++) {
            int gp = pix_base + t * 128 + prow + i * 32;
            int n = gp / PIX_PER_IMG;
            int r = gp % PIX_PER_IMG;
            hA[t * 4 + i] = r / HW_DIM;
            wA[t * 4 + i] = r % HW_DIM;
            rowA[t * 4 + i] = (size_t)n * PIX_PER_IMG * C_IN;
        }
    }

    // async fill of one chunk-stage (256 producer threads, 16 cp.async each)
    auto fill_stage = [&](int c, int buf) {
        int tap = c >> 1, half_k = c & 1;
        int kh = tap / 3 - 1, kw = tap % 3 - 1;
        uint32_t sb = smem_base + SM_STAGE + buf * STAGE_BYTES;
        #pragma unroll
        for (int t = 0; t < 2; t++) {
            #pragma unroll
            for (int i = 0; i < 4; i++) {
                int idx = t * 4 + i;
                int hh = hA[idx] + kh, ww = wA[idx] + kw;
                bool ok = ((unsigned)hh < (unsigned)HW_DIM) &&
                          ((unsigned)ww < (unsigned)HW_DIM);
                const __half* src = Xh_g + rowA[idx] +
                    ((size_t)(ok ? hh : 0) * HW_DIM + (ok ? ww : 0)) * C_IN +
                    half_k * 64 + seg * 8;
                uint32_t off = (uint32_t)(prow + i * 32) * 128 + seg * 16;
                cp_async16z(sb + t * A_TILE_B + SW128(off), src, ok);
            }
        }
        const __half* wsrc = Wq_g + (size_t)c * (C_OUT * K_CHUNK);
        int base = tid & 255;
        #pragma unroll
        for (int i = 0; i < 8; i++) {
            int item = base + i * 256;            // 0..2047
            uint32_t off = (uint32_t)(item >> 3) * 128 + (item & 7) * 16;
            cp_async16(sb + B_OFF + SW128(off), wsrc + item * 8);
        }
    };

    bool producer = (tid < 256);

    // prologue: producers fill stages 0,1,2 and tag each with a noinc arrive
    if (producer) {
        fill_stage(0, 0); CP_ASYNC_MBAR_ARRIVE(smem_base + SM_FMBAR + 0);
        fill_stage(1, 1); CP_ASYNC_MBAR_ARRIVE(smem_base + SM_FMBAR + 8);
        fill_stage(2, 2); CP_ASYNC_MBAR_ARRIVE(smem_base + SM_FMBAR + 16);
    }

    #pragma unroll 1
    for (int c = 0; c < NUM_CHUNKS; c++) {
        int s = c % 3;
        int par = (c / 3) & 1;

        if (wid == 8) {
            // MMA warp: wait fill(c), fence, issue, commit
            MBARRIER_WAIT_PARITY(smem_base + SM_FMBAR + s * 8, par);
            if (elect_one()) {
                FENCE_PROXY_ASYNC_SHARED();
                uint32_t sb = smem_base + SM_STAGE + s * STAGE_BYTES;
                uint64_t a0 = make_desc_sw128(sb);
                uint64_t a1 = make_desc_sw128(sb + A_TILE_B);
                uint64_t bd = make_desc_sw128(sb + B_OFF);
                uint32_t en = (c > 0);
                #pragma unroll
                for (int q = 0; q < 4; q++)
                    mma_f16_ss(tmem_base, a0 + q * 2, bd + q * 2,
                               MMA_IDESC, en | (q > 0));
                #pragma unroll
                for (int q = 0; q < 4; q++)
                    mma_f16_ss(tmem_base + 256, a1 + q * 2, bd + q * 2,
                               MMA_IDESC, en | (q > 0));
                TCGEN05_COMMIT(smem_base + SM_MMBAR + s * 8);
            }
        } else if (producer && c + 3 < NUM_CHUNKS) {
            // producers: stage s free once MMA(c) completed
            MBARRIER_WAIT_PARITY(smem_base + SM_MMBAR + s * 8, par);
            fill_stage(c + 3, s);
            CP_ASYNC_MBAR_ARRIVE(smem_base + SM_FMBAR + s * 8);
        }
    }

    // drain: commit(17) implies all prior MMAs complete (mbar 2, phase 5)
    MBARRIER_WAIT_PARITY(smem_base + SM_MMBAR + 16, 1);
    TCGEN05_FENCE_AFTER();

    // ---- epilogue: warp-private transpose (warps 0-7), no block barriers ----
    float* bsm = reinterpret_cast<float*>(smem + SM_BIAS);
    if (producer) bsm[tid] = bias[tid];
    __syncthreads();

    if (wid < 8) {
        int wg = wid >> 2;                        // tile index (0/1)
        int sp = wid & 3;                         // subpartition (row group)
        uint32_t tbw = smem_base + SM_TBUF + (uint32_t)wid * 4096;
        int prow_g = pix_base + wg * 128 + sp * 32;

        #pragma unroll 1
        for (int cb = 0; cb < 8; cb++) {
            uint32_t regs[32];
            TCGEN05_LD_32X32B_X32(regs, tmem_base + wg * 256 + cb * 32);
            TCGEN05_WAIT_LD();
            #pragma unroll
            for (int k = 0; k < 8; k++) {
                uint32_t a0 = __float_as_uint(__uint_as_float(regs[4 * k + 0]) + bsm[cb * 32 + 4 * k + 0]);
                uint32_t a1 = __float_as_uint(__uint_as_float(regs[4 * k + 1]) + bsm[cb * 32 + 4 * k + 1]);
                uint32_t a2 = __float_as_uint(__uint_as_float(regs[4 * k + 2]) + bsm[cb * 32 + 4 * k + 2]);
                uint32_t a3 = __float_as_uint(__uint_as_float(regs[4 * k + 3]) + bsm[cb * 32 + 4 * k + 3]);
                sts128(tbw + (uint32_t)lid * 128 + (((k + lid) & 7) << 4), a0, a1, a2, a3);
            }
            __syncwarp();
            #pragma unroll
            for (int k = 0; k < 8; k++) {
                int p = k * 4 + (lid >> 3);
                int cc = lid & 7;
                uint32_t r0, r1, r2, r3;
                lds128(tbw + (uint32_t)p * 128 + (((cc + p) & 7) << 4), r0, r1, r2, r3);
                float4 v = make_float4(__uint_as_float(r0), __uint_as_float(r1),
                                       __uint_as_float(r2), __uint_as_float(r3));
                *reinterpret_cast<float4*>(
                    out + (size_t)(prow_g + p) * C_OUT + cb * 32 + cc * 4) = v;
            }
            __syncwarp();
        }
    }

    __syncthreads();                              // no warp may still touch TMEM
    if (wid == 0) {
        TCGEN05_DEALLOC(tmem_base, 512);
    }
}

// ---------------- launch ----------------
extern "C" void kernel_launch(void* const* d_in, const int* in_sizes, int n_in,
                              void* d_out, int out_size) {
    const float* x = (const float*)d_in[0];
    const float* W = (const float*)d_in[1];
    const float* b = (const float*)d_in[2];
    float* out = (float*)d_out;

    cudaFuncSetAttribute(bconv_main_kernel,
                         cudaFuncAttributeMaxDynamicSharedMemorySize, SM_TOTAL);

    int n4 = (TOT_PIX * C_IN) / 4;
    convert_x_kernel<<<n4 / 256, 256>>>(reinterpret_cast<const float4*>(x), n4);
    quant_w_kernel<<<(NUM_CHUNKS * C_OUT * K_CHUNK) / 256, 256>>>(W);
    bconv_main_kernel<<<NUM_PAIRS, NTHREADS, SM_TOTAL>>>(b, out);
}